// round 15
// baseline (speedup 1.0000x reference)
#include <cuda_runtime.h>
#include <cuda_fp16.h>

#define HEADS 8
#define D 256
#define NCAP 32768
#define MCAP 327680

// Segment-sum scratch, packed: seg[(node*b + bb)*HEADS + h]. 2MB slack.
__device__ float g_seg[1 << 19];

// fp16 mirror of k (unscaled; q carries the 1/16 softmax scale).
#define K_CAP 10485760
__device__ __half g_kh[K_CAP];

// counting-sort / CSR scratch (16B aligned for int4 access)
__device__ __align__(16) int  g_cnt[NCAP];     // zeroed by scan each call
__device__ __align__(16) int  g_ofs[NCAP + 4]; // CSR row start + sentinel
__device__ __align__(16) int  g_cur[NCAP];     // scatter cursor
// {k_byteoff, ex_byteoff, seg_byteoff, 0} grouped by q-node
__device__ int4 g_edges[MCAP];

// Zero seg; histogram e0; convert k -> fp16.
__global__ void __launch_bounds__(256) prep_kernel(
    const float4* __restrict__ k,
    const int* __restrict__ e0, int m, int n16, int segcount)
{
    int i = blockIdx.x * blockDim.x + threadIdx.x;
    int stride = gridDim.x * blockDim.x;

    for (int s = i; s < segcount; s += stride) g_seg[s] = 0.0f;
    for (int j = i; j < m; j += stride) atomicAdd(&g_cnt[e0[j]], 1);

    uint4* kh = (uint4*)g_kh;
    for (int j = i; j < n16; j += stride) {
        float4 v0 = k[2 * j], v1 = k[2 * j + 1];
        __half2 h0 = __floats2half2_rn(v0.x, v0.y);
        __half2 h1 = __floats2half2_rn(v0.z, v0.w);
        __half2 h2 = __floats2half2_rn(v1.x, v1.y);
        __half2 h3 = __floats2half2_rn(v1.z, v1.w);
        uint4 u;
        u.x = *(unsigned*)&h0; u.y = *(unsigned*)&h1;
        u.z = *(unsigned*)&h2; u.w = *(unsigned*)&h3;
        kh[j] = u;
    }
}

// Single-block exclusive scan, 4 elements/thread (int4). Re-zeroes g_cnt.
__global__ void __launch_bounds__(1024) scan_kernel(int n)
{
    __shared__ int wsum[32];
    __shared__ int wexcl[32];
    __shared__ int s_carry;
    int tid = threadIdx.x, lane = tid & 31, wid = tid >> 5;
    if (tid == 0) s_carry = 0;
    __syncthreads();

    int nt = (n + 4095) >> 12;
    for (int tb = 0; tb < nt; tb++) {
        int i4 = (tb << 12) + (tid << 2);
        int4 c = *(const int4*)&g_cnt[i4];
        *(int4*)&g_cnt[i4] = make_int4(0, 0, 0, 0);
        int lsum = c.x + c.y + c.z + c.w;
        int s = lsum;
        #pragma unroll
        for (int off = 1; off < 32; off <<= 1) {
            int t = __shfl_up_sync(0xffffffffu, s, off);
            if (lane >= off) s += t;
        }
        if (lane == 31) wsum[wid] = s;
        __syncthreads();
        if (wid == 0) {
            int w = wsum[lane];
            int ws = w;
            #pragma unroll
            for (int off = 1; off < 32; off <<= 1) {
                int t = __shfl_up_sync(0xffffffffu, ws, off);
                if (lane >= off) ws += t;
            }
            wexcl[lane] = ws - w;
        }
        __syncthreads();
        int excl = (s - lsum) + wexcl[wid] + s_carry;
        int o0 = excl, o1 = o0 + c.x, o2 = o1 + c.y, o3 = o2 + c.z;
        *(int4*)&g_ofs[i4] = make_int4(o0, o1, o2, o3);
        *(int4*)&g_cur[i4] = make_int4(o0, o1, o2, o3);
        __syncthreads();
        if (tid == 1023) s_carry = excl + lsum;
        __syncthreads();
    }
    if (tid == 0) g_ofs[n] = s_carry;          // sentinel
}

// Scatter edges grouped by q-node, storing precomputed byte offsets.
__global__ void __launch_bounds__(256) scatter_kernel(
    const int* __restrict__ e0, const int* __restrict__ e1,
    const int* __restrict__ r, int m, int b)
{
    int t = blockIdx.x * blockDim.x + threadIdx.x;
    int j0 = t * 4;
    if (j0 >= m) return;

    if (j0 + 4 <= m) {
        int4 q4 = *(const int4*)(e0 + j0);
        int4 k4 = *(const int4*)(e1 + j0);
        int4 r4 = *(const int4*)(r + j0);
        int p0 = atomicAdd(&g_cur[q4.x], 1);
        int p1 = atomicAdd(&g_cur[q4.y], 1);
        int p2 = atomicAdd(&g_cur[q4.z], 1);
        int p3 = atomicAdd(&g_cur[q4.w], 1);
        int b32 = b * 32;
        g_edges[p0] = make_int4(k4.x << 9, (j0 + 0) << 5, r4.x * b32, 0);
        g_edges[p1] = make_int4(k4.y << 9, (j0 + 1) << 5, r4.y * b32, 0);
        g_edges[p2] = make_int4(k4.z << 9, (j0 + 2) << 5, r4.z * b32, 0);
        g_edges[p3] = make_int4(k4.w << 9, (j0 + 3) << 5, r4.w * b32, 0);
    } else {
        for (int j = j0; j < m; j++) {
            int pos = atomicAdd(&g_cur[e0[j]], 1);
            g_edges[pos] = make_int4(e1[j] << 9, j << 5, r[j] * b * 32, 0);
        }
    }
}

// fp16 dot of 16 dims: 8 HFMA2-class ops into one half2 acc, fp32 fix-up.
// Magnitudes are small (q pre-scaled by 1/16) -> fp16 acc error ~1e-4 abs.
__device__ __forceinline__ float dot16h(uint4 qa, uint4 qb, uint4 ka, uint4 kb) {
    const __half2* qa2 = (const __half2*)&qa;
    const __half2* qb2 = (const __half2*)&qb;
    const __half2* ka2 = (const __half2*)&ka;
    const __half2* kb2 = (const __half2*)&kb;
    __half2 acc = __hmul2(qa2[0], ka2[0]);
    acc = __hfma2(qa2[1], ka2[1], acc);
    acc = __hfma2(qa2[2], ka2[2], acc);
    acc = __hfma2(qa2[3], ka2[3], acc);
    acc = __hfma2(qb2[0], kb2[0], acc);
    acc = __hfma2(qb2[1], kb2[1], acc);
    acc = __hfma2(qb2[2], kb2[2], acc);
    acc = __hfma2(qb2[3], kb2[3], acc);
    float2 f = __half22float2(acc);
    return f.x + f.y;
}

// A1 (b==2): one warp per q-node; lanes = (edge e=lane>>4, head h=(lane>>1)&7,
// half=lane&1). q row staged via smem (scaled by 1/16, fp16), each lane holds
// its 16 dims x 2 batches in 4 loop-invariant uint4 regs. Per 2-edge iter:
// 1 record load, 4 k loads/lane, 16 HFMA2, ONE shfl per batch, dense epilogue.
__global__ void __launch_bounds__(256) passA1_b2_kernel(
    const float4* __restrict__ q,
    float* __restrict__ ex_out, int n, int m)
{
    __shared__ __align__(16) char qsm[8][2][512];

    int wid = threadIdx.x >> 5, lane = threadIdx.x & 31;
    int v = blockIdx.x * 8 + wid;
    if (v >= n) return;

    int start = g_ofs[v];
    int cnt = g_ofs[v + 1] - start;
    if (cnt == 0) return;

    // --- stage q (both batches) into smem as scaled fp16, chunk-major ---
    {
        long long qrow = (long long)v * (D / 4) + lane * 2;
        long long qbs = (long long)n * (D / 4);
        const float SC = 0.0625f;   // 1/sqrt(KEY_DIM)... = 1/16 folded into q
        // lane covers dims [8*lane, 8*lane+8): j=lane&1, slot=(lane>>2)*2+((lane>>1)&1)
        int saddr = ((lane & 1) << 8) + ((((lane >> 2) << 1) | ((lane >> 1) & 1)) << 4);
        #pragma unroll
        for (int bb = 0; bb < 2; bb++) {
            float4 a = q[qrow + bb * qbs];
            float4 c = q[qrow + bb * qbs + 1];
            __half2 h0 = __floats2half2_rn(a.x * SC, a.y * SC);
            __half2 h1 = __floats2half2_rn(a.z * SC, a.w * SC);
            __half2 h2 = __floats2half2_rn(c.x * SC, c.y * SC);
            __half2 h3 = __floats2half2_rn(c.z * SC, c.w * SC);
            uint4 u;
            u.x = *(unsigned*)&h0; u.y = *(unsigned*)&h1;
            u.z = *(unsigned*)&h2; u.w = *(unsigned*)&h3;
            *(uint4*)(qsm[wid][bb] + saddr) = u;
        }
    }
    __syncwarp();

    int h = (lane >> 1) & 7;
    int half = lane & 1;
    int e = lane >> 4;

    // lane's loop-invariant q registers: slot = h*2+half, chunks j=0,1
    int rbase = ((h << 1) | half) << 4;
    uint4 q00 = *(const uint4*)(qsm[wid][0] + rbase);
    uint4 q01 = *(const uint4*)(qsm[wid][0] + 256 + rbase);
    uint4 q10 = *(const uint4*)(qsm[wid][1] + rbase);
    uint4 q11 = *(const uint4*)(qsm[wid][1] + 256 + rbase);

    const char* kb = (const char*)g_kh;
    char* exb = (char*)ex_out;
    char* segb = (char*)g_seg;
    int kbs = n << 9;                   // bytes between k batches
    int exb1 = m << 5;                  // batch-1 ex byte offset
    int klo = (h << 6) + (half << 5);   // within-row byte offset of lane's 16 dims
    int h4 = h << 2;
    bool wlane = (half == 0);
    int last = cnt - 1;

    for (int t = 0; t < cnt; t += 2) {
        int idx = t + e;
        int rid = idx < last ? idx : last;
        bool act = wlane && (idx < cnt);
        int4 ed = g_edges[start + rid];

        int ko = ed.x + klo;
        uint4 ka0 = *(const uint4*)(kb + ko);
        uint4 ka1 = *(const uint4*)(kb + ko + 16);
        uint4 kc0 = *(const uint4*)(kb + ko + kbs);
        uint4 kc1 = *(const uint4*)(kb + ko + kbs + 16);

        float s0 = dot16h(q00, q01, ka0, ka1);
        float s1 = dot16h(q10, q11, kc0, kc1);

        // combine the two half-head lanes (single shuffle per batch)
        s0 += __shfl_xor_sync(0xffffffffu, s0, 1);
        s1 += __shfl_xor_sync(0xffffffffu, s1, 1);

        // a = dot/sqrt(256) (scale folded into q); global max-shift dropped:
        // ratio is shift-invariant, exp(a) <= ~8, eps below fp32 ulp of denom.
        float ex0 = __expf(s0);
        float ex1 = __expf(s1);

        if (act) {
            *(float*)(exb + ed.y + h4) = ex0;
            *(float*)(exb + ed.y + exb1 + h4) = ex1;
            atomicAdd((float*)(segb + ed.z + h4), ex0);
            atomicAdd((float*)(segb + ed.z + 32 + h4), ex1);
        }
    }
}

// Generic-b fallback (correctness path; b==2 uses the kernel above).
__device__ __forceinline__ float dotqk_g(float4 qa, float4 qb, uint4 uk) {
    float s = 0.0f;
    float2 c;
    c = __half22float2(*(const __half2*)&uk.x); s += qa.x * c.x + qa.y * c.y;
    c = __half22float2(*(const __half2*)&uk.y); s += qa.z * c.x + qa.w * c.y;
    c = __half22float2(*(const __half2*)&uk.z); s += qb.x * c.x + qb.y * c.y;
    c = __half22float2(*(const __half2*)&uk.w); s += qb.z * c.x + qb.w * c.y;
    return s;
}

__global__ void __launch_bounds__(256) passA1_gen_kernel(
    const float4* __restrict__ q,
    float* __restrict__ ex_out, int n, int m, int b)
{
    int v = blockIdx.x * (blockDim.x >> 5) + (threadIdx.x >> 5);
    int lane = threadIdx.x & 31;
    if (v >= n) return;

    int start = g_ofs[v];
    int cnt = g_ofs[v + 1] - start;
    if (cnt == 0) return;

    const char* kb = (const char*)g_kh;
    char* exb = (char*)ex_out;
    char* segb = (char*)g_seg;
    int lane16 = lane * 16;
    int kbstride = n << 9;
    bool wr = (lane & 3) == 0;
    int h4 = lane & 28;
    long long qrow = (long long)v * (D / 4) + lane * 2;
    long long qbs = (long long)n * (D / 4);

    for (int t = 0; t < cnt; t++) {
        int4 ed = g_edges[start + t];
        for (int bb = 0; bb < b; bb++) {
            float4 qa = q[qrow + bb * qbs];
            float4 qb = q[qrow + bb * qbs + 1];
            uint4 uk = *(const uint4*)(kb + ed.x + lane16 + bb * kbstride);
            float s = dotqk_g(qa, qb, uk);
            s += __shfl_xor_sync(0xffffffffu, s, 1);
            s += __shfl_xor_sync(0xffffffffu, s, 2);
            float ex = __expf(s * 0.0625f);
            if (wr) {
                *(float*)(exb + ed.y + (long long)bb * (m << 5) + h4) = ex;
                atomicAdd((float*)(segb + ed.z + bb * 32 + h4), ex);
            }
        }
    }
}

// B: one thread per (batch, edge): normalize 8 heads.
__global__ void __launch_bounds__(256) passB_kernel(
    const int* __restrict__ r, float* __restrict__ out, int m, int b)
{
    int i = blockIdx.x * blockDim.x + threadIdx.x;
    if (i >= m * b) return;
    int bb = i / m;
    int mm = i - bb * m;
    int rr = r[mm];

    const float4* segp = (const float4*)&g_seg[(((long long)rr * b + bb) << 3)];
    float4 s0 = segp[0], s1 = segp[1];

    float4* op = (float4*)(out + ((long long)i << 3));
    float4 v0 = op[0], v1 = op[1];

    v0.x /= (s0.x + 1e-16f); v0.y /= (s0.y + 1e-16f);
    v0.z /= (s0.z + 1e-16f); v0.w /= (s0.w + 1e-16f);
    v1.x /= (s1.x + 1e-16f); v1.y /= (s1.y + 1e-16f);
    v1.z /= (s1.z + 1e-16f); v1.w /= (s1.w + 1e-16f);

    op[0] = v0; op[1] = v1;
}

extern "C" void kernel_launch(void* const* d_in, const int* in_sizes, int n_in,
                              void* d_out, int out_size) {
    const float* q = (const float*)d_in[0];
    const float* k = (const float*)d_in[1];
    const int*   e = (const int*)d_in[2];
    const int*   r = (const int*)d_in[3];
    float* out = (float*)d_out;

    int m = in_sizes[3];                    // r has m elements
    int b = out_size / (m * HEADS);         // output is (b, m, HEADS)
    int n = in_sizes[0] / (b * D);          // q is (b, n, D)

    const int* e0 = e;
    const int* e1 = e + m;

    int seg_count = n * b * HEADS;
    int n16 = (b * n * D) / 8;              // 16-byte half chunks of k
    prep_kernel<<<4000, 256>>>((const float4*)k, e0, m, n16, seg_count);

    scan_kernel<<<1, 1024>>>(n);
    scatter_kernel<<<((m + 3) / 4 + 255) / 256, 256>>>(e0, e1, r, m, b);

    if (b == 2) {
        passA1_b2_kernel<<<(n + 7) / 8, 256>>>((const float4*)q, out, n, m);
    } else {
        passA1_gen_kernel<<<(n + 7) / 8, 256>>>((const float4*)q, out, n, m, b);
    }

    int mb = m * b;
    passB_kernel<<<(mb + 255) / 256, 256>>>(r, out, m, b);
}

// round 16
// speedup vs baseline: 1.0234x; 1.0234x over previous
#include <cuda_runtime.h>
#include <cuda_fp16.h>

#define HEADS 8
#define D 256
#define NCAP 32768
#define MCAP 327680

// Segment-sum scratch, packed: seg[(node*b + bb)*HEADS + h]. 2MB slack.
__device__ float g_seg[1 << 19];

// fp16 mirror of k (unscaled; q carries the 1/16 softmax scale).
#define K_CAP 10485760
__device__ __half g_kh[K_CAP];

// counting-sort / CSR scratch (16B aligned for int4 access)
__device__ __align__(16) int  g_cnt[NCAP];     // zeroed by scan each call
__device__ __align__(16) int  g_ofs[NCAP + 4]; // CSR row start + sentinel
__device__ __align__(16) int  g_cur[NCAP];     // scatter cursor
// {k_byteoff, ex_byteoff, seg_byteoff, 0} grouped by q-node
__device__ int4 g_edges[MCAP];

// Zero seg; histogram e0; convert k -> fp16.
__global__ void __launch_bounds__(256) prep_kernel(
    const float4* __restrict__ k,
    const int* __restrict__ e0, int m, int n16, int segcount)
{
    int i = blockIdx.x * blockDim.x + threadIdx.x;
    int stride = gridDim.x * blockDim.x;

    for (int s = i; s < segcount; s += stride) g_seg[s] = 0.0f;
    for (int j = i; j < m; j += stride) atomicAdd(&g_cnt[e0[j]], 1);

    uint4* kh = (uint4*)g_kh;
    for (int j = i; j < n16; j += stride) {
        float4 v0 = k[2 * j], v1 = k[2 * j + 1];
        __half2 h0 = __floats2half2_rn(v0.x, v0.y);
        __half2 h1 = __floats2half2_rn(v0.z, v0.w);
        __half2 h2 = __floats2half2_rn(v1.x, v1.y);
        __half2 h3 = __floats2half2_rn(v1.z, v1.w);
        uint4 u;
        u.x = *(unsigned*)&h0; u.y = *(unsigned*)&h1;
        u.z = *(unsigned*)&h2; u.w = *(unsigned*)&h3;
        kh[j] = u;
    }
}

// Single-block exclusive scan, 4 elements/thread (int4). Re-zeroes g_cnt.
__global__ void __launch_bounds__(1024) scan_kernel(int n)
{
    __shared__ int wsum[32];
    __shared__ int wexcl[32];
    __shared__ int s_carry;
    int tid = threadIdx.x, lane = tid & 31, wid = tid >> 5;
    if (tid == 0) s_carry = 0;
    __syncthreads();

    int nt = (n + 4095) >> 12;
    for (int tb = 0; tb < nt; tb++) {
        int i4 = (tb << 12) + (tid << 2);
        int4 c = *(const int4*)&g_cnt[i4];
        *(int4*)&g_cnt[i4] = make_int4(0, 0, 0, 0);
        int lsum = c.x + c.y + c.z + c.w;
        int s = lsum;
        #pragma unroll
        for (int off = 1; off < 32; off <<= 1) {
            int t = __shfl_up_sync(0xffffffffu, s, off);
            if (lane >= off) s += t;
        }
        if (lane == 31) wsum[wid] = s;
        __syncthreads();
        if (wid == 0) {
            int w = wsum[lane];
            int ws = w;
            #pragma unroll
            for (int off = 1; off < 32; off <<= 1) {
                int t = __shfl_up_sync(0xffffffffu, ws, off);
                if (lane >= off) ws += t;
            }
            wexcl[lane] = ws - w;
        }
        __syncthreads();
        int excl = (s - lsum) + wexcl[wid] + s_carry;
        int o0 = excl, o1 = o0 + c.x, o2 = o1 + c.y, o3 = o2 + c.z;
        *(int4*)&g_ofs[i4] = make_int4(o0, o1, o2, o3);
        *(int4*)&g_cur[i4] = make_int4(o0, o1, o2, o3);
        __syncthreads();
        if (tid == 1023) s_carry = excl + lsum;
        __syncthreads();
    }
    if (tid == 0) g_ofs[n] = s_carry;          // sentinel
}

// Scatter edges grouped by q-node, storing precomputed byte offsets.
__global__ void __launch_bounds__(256) scatter_kernel(
    const int* __restrict__ e0, const int* __restrict__ e1,
    const int* __restrict__ r, int m, int b)
{
    int t = blockIdx.x * blockDim.x + threadIdx.x;
    int j0 = t * 4;
    if (j0 >= m) return;

    if (j0 + 4 <= m) {
        int4 q4 = *(const int4*)(e0 + j0);
        int4 k4 = *(const int4*)(e1 + j0);
        int4 r4 = *(const int4*)(r + j0);
        int p0 = atomicAdd(&g_cur[q4.x], 1);
        int p1 = atomicAdd(&g_cur[q4.y], 1);
        int p2 = atomicAdd(&g_cur[q4.z], 1);
        int p3 = atomicAdd(&g_cur[q4.w], 1);
        int b32 = b * 32;
        g_edges[p0] = make_int4(k4.x << 9, (j0 + 0) << 5, r4.x * b32, 0);
        g_edges[p1] = make_int4(k4.y << 9, (j0 + 1) << 5, r4.y * b32, 0);
        g_edges[p2] = make_int4(k4.z << 9, (j0 + 2) << 5, r4.z * b32, 0);
        g_edges[p3] = make_int4(k4.w << 9, (j0 + 3) << 5, r4.w * b32, 0);
    } else {
        for (int j = j0; j < m; j++) {
            int pos = atomicAdd(&g_cur[e0[j]], 1);
            g_edges[pos] = make_int4(e1[j] << 9, j << 5, r[j] * b * 32, 0);
        }
    }
}

// fp16 dot of 16 dims: 8 HFMA2-class ops into one half2 acc, fp32 fix-up.
__device__ __forceinline__ float dot16h(uint4 qa, uint4 qb, uint4 ka, uint4 kb) {
    const __half2* qa2 = (const __half2*)&qa;
    const __half2* qb2 = (const __half2*)&qb;
    const __half2* ka2 = (const __half2*)&ka;
    const __half2* kb2 = (const __half2*)&kb;
    __half2 acc = __hmul2(qa2[0], ka2[0]);
    acc = __hfma2(qa2[1], ka2[1], acc);
    acc = __hfma2(qa2[2], ka2[2], acc);
    acc = __hfma2(qa2[3], ka2[3], acc);
    acc = __hfma2(qb2[0], kb2[0], acc);
    acc = __hfma2(qb2[1], kb2[1], acc);
    acc = __hfma2(qb2[2], kb2[2], acc);
    acc = __hfma2(qb2[3], kb2[3], acc);
    float2 f = __half22float2(acc);
    return f.x + f.y;
}

// A1 (b==2): one warp per q-node; lanes = (edge e=lane>>4, head h=(lane>>1)&7,
// half=lane&1). SOFTWARE-PIPELINED one iteration deep: the next edge-pair's
// record + k-row loads are issued before the current pair's compute, hiding
// the L2 gather latency behind compute.
__global__ void __launch_bounds__(256) passA1_b2_kernel(
    const float4* __restrict__ q,
    float* __restrict__ ex_out, int n, int m)
{
    __shared__ __align__(16) char qsm[8][2][512];

    int wid = threadIdx.x >> 5, lane = threadIdx.x & 31;
    int v = blockIdx.x * 8 + wid;
    if (v >= n) return;

    int start = g_ofs[v];
    int cnt = g_ofs[v + 1] - start;
    if (cnt == 0) return;

    // --- stage q (both batches) into smem as scaled fp16, chunk-major ---
    {
        long long qrow = (long long)v * (D / 4) + lane * 2;
        long long qbs = (long long)n * (D / 4);
        const float SC = 0.0625f;   // softmax 1/16 folded into q
        int saddr = ((lane & 1) << 8) + ((((lane >> 2) << 1) | ((lane >> 1) & 1)) << 4);
        #pragma unroll
        for (int bb = 0; bb < 2; bb++) {
            float4 a = q[qrow + bb * qbs];
            float4 c = q[qrow + bb * qbs + 1];
            __half2 h0 = __floats2half2_rn(a.x * SC, a.y * SC);
            __half2 h1 = __floats2half2_rn(a.z * SC, a.w * SC);
            __half2 h2 = __floats2half2_rn(c.x * SC, c.y * SC);
            __half2 h3 = __floats2half2_rn(c.z * SC, c.w * SC);
            uint4 u;
            u.x = *(unsigned*)&h0; u.y = *(unsigned*)&h1;
            u.z = *(unsigned*)&h2; u.w = *(unsigned*)&h3;
            *(uint4*)(qsm[wid][bb] + saddr) = u;
        }
    }
    __syncwarp();

    int h = (lane >> 1) & 7;
    int half = lane & 1;
    int e = lane >> 4;

    int rbase = ((h << 1) | half) << 4;
    uint4 q00 = *(const uint4*)(qsm[wid][0] + rbase);
    uint4 q01 = *(const uint4*)(qsm[wid][0] + 256 + rbase);
    uint4 q10 = *(const uint4*)(qsm[wid][1] + rbase);
    uint4 q11 = *(const uint4*)(qsm[wid][1] + 256 + rbase);

    const char* kb = (const char*)g_kh;
    char* exb = (char*)ex_out;
    char* segb = (char*)g_seg;
    int kbs = n << 9;                   // bytes between k batches
    int exb1 = m << 5;                  // batch-1 ex byte offset
    int klo = (h << 6) + (half << 5);   // within-row byte offset of lane's 16 dims
    int h4 = h << 2;
    bool wlane = (half == 0);
    int last = cnt - 1;

    // ---- prologue: load iteration 0 ----
    int idx = e < last ? e : last;
    int4 ed = g_edges[start + idx];
    int ko = ed.x + klo;
    uint4 ka0 = *(const uint4*)(kb + ko);
    uint4 ka1 = *(const uint4*)(kb + ko + 16);
    uint4 kc0 = *(const uint4*)(kb + ko + kbs);
    uint4 kc1 = *(const uint4*)(kb + ko + kbs + 16);

    for (int t = 0; t < cnt; t += 2) {
        // ---- prefetch iteration t+2 (clamped; harmless re-load at tail) ----
        int nidxr = t + 2 + e;
        int nidx = nidxr < last ? nidxr : last;
        int4 edn = g_edges[start + nidx];
        int kon = edn.x + klo;
        uint4 na0 = *(const uint4*)(kb + kon);
        uint4 na1 = *(const uint4*)(kb + kon + 16);
        uint4 nc0 = *(const uint4*)(kb + kon + kbs);
        uint4 nc1 = *(const uint4*)(kb + kon + kbs + 16);

        // ---- compute current pair ----
        float s0 = dot16h(q00, q01, ka0, ka1);
        float s1 = dot16h(q10, q11, kc0, kc1);
        s0 += __shfl_xor_sync(0xffffffffu, s0, 1);
        s1 += __shfl_xor_sync(0xffffffffu, s1, 1);

        // a = dot/sqrt(256) (scale folded into q); global max-shift dropped:
        // ratio is shift-invariant, exp(a) <= ~8, eps below fp32 ulp of denom.
        float ex0 = __expf(s0);
        float ex1 = __expf(s1);

        if (wlane && (t + e < cnt)) {
            *(float*)(exb + ed.y + h4) = ex0;
            *(float*)(exb + ed.y + exb1 + h4) = ex1;
            atomicAdd((float*)(segb + ed.z + h4), ex0);
            atomicAdd((float*)(segb + ed.z + 32 + h4), ex1);
        }

        // ---- rotate pipeline ----
        ed = edn;
        ka0 = na0; ka1 = na1; kc0 = nc0; kc1 = nc1;
    }
}

// Generic-b fallback (correctness path; b==2 uses the kernel above).
__device__ __forceinline__ float dotqk_g(float4 qa, float4 qb, uint4 uk) {
    float s = 0.0f;
    float2 c;
    c = __half22float2(*(const __half2*)&uk.x); s += qa.x * c.x + qa.y * c.y;
    c = __half22float2(*(const __half2*)&uk.y); s += qa.z * c.x + qa.w * c.y;
    c = __half22float2(*(const __half2*)&uk.z); s += qb.x * c.x + qb.y * c.y;
    c = __half22float2(*(const __half2*)&uk.w); s += qb.z * c.x + qb.w * c.y;
    return s;
}

__global__ void __launch_bounds__(256) passA1_gen_kernel(
    const float4* __restrict__ q,
    float* __restrict__ ex_out, int n, int m, int b)
{
    int v = blockIdx.x * (blockDim.x >> 5) + (threadIdx.x >> 5);
    int lane = threadIdx.x & 31;
    if (v >= n) return;

    int start = g_ofs[v];
    int cnt = g_ofs[v + 1] - start;
    if (cnt == 0) return;

    const char* kb = (const char*)g_kh;
    char* exb = (char*)ex_out;
    char* segb = (char*)g_seg;
    int lane16 = lane * 16;
    int kbstride = n << 9;
    bool wr = (lane & 3) == 0;
    int h4 = lane & 28;
    long long qrow = (long long)v * (D / 4) + lane * 2;
    long long qbs = (long long)n * (D / 4);

    for (int t = 0; t < cnt; t++) {
        int4 ed = g_edges[start + t];
        for (int bb = 0; bb < b; bb++) {
            float4 qa = q[qrow + bb * qbs];
            float4 qb = q[qrow + bb * qbs + 1];
            uint4 uk = *(const uint4*)(kb + ed.x + lane16 + bb * kbstride);
            float s = dotqk_g(qa, qb, uk);
            s += __shfl_xor_sync(0xffffffffu, s, 1);
            s += __shfl_xor_sync(0xffffffffu, s, 2);
            float ex = __expf(s * 0.0625f);
            if (wr) {
                *(float*)(exb + ed.y + (long long)bb * (m << 5) + h4) = ex;
                atomicAdd((float*)(segb + ed.z + bb * 32 + h4), ex);
            }
        }
    }
}

// B: one thread per (batch, edge): normalize 8 heads.
__global__ void __launch_bounds__(256) passB_kernel(
    const int* __restrict__ r, float* __restrict__ out, int m, int b)
{
    int i = blockIdx.x * blockDim.x + threadIdx.x;
    if (i >= m * b) return;
    int bb = i / m;
    int mm = i - bb * m;
    int rr = r[mm];

    const float4* segp = (const float4*)&g_seg[(((long long)rr * b + bb) << 3)];
    float4 s0 = segp[0], s1 = segp[1];

    float4* op = (float4*)(out + ((long long)i << 3));
    float4 v0 = op[0], v1 = op[1];

    v0.x /= (s0.x + 1e-16f); v0.y /= (s0.y + 1e-16f);
    v0.z /= (s0.z + 1e-16f); v0.w /= (s0.w + 1e-16f);
    v1.x /= (s1.x + 1e-16f); v1.y /= (s1.y + 1e-16f);
    v1.z /= (s1.z + 1e-16f); v1.w /= (s1.w + 1e-16f);

    op[0] = v0; op[1] = v1;
}

extern "C" void kernel_launch(void* const* d_in, const int* in_sizes, int n_in,
                              void* d_out, int out_size) {
    const float* q = (const float*)d_in[0];
    const float* k = (const float*)d_in[1];
    const int*   e = (const int*)d_in[2];
    const int*   r = (const int*)d_in[3];
    float* out = (float*)d_out;

    int m = in_sizes[3];                    // r has m elements
    int b = out_size / (m * HEADS);         // output is (b, m, HEADS)
    int n = in_sizes[0] / (b * D);          // q is (b, n, D)

    const int* e0 = e;
    const int* e1 = e + m;

    int seg_count = n * b * HEADS;
    int n16 = (b * n * D) / 8;              // 16-byte half chunks of k
    prep_kernel<<<4000, 256>>>((const float4*)k, e0, m, n16, seg_count);

    scan_kernel<<<1, 1024>>>(n);
    scatter_kernel<<<((m + 3) / 4 + 255) / 256, 256>>>(e0, e1, r, m, b);

    if (b == 2) {
        passA1_b2_kernel<<<(n + 7) / 8, 256>>>((const float4*)q, out, n, m);
    } else {
        passA1_gen_kernel<<<(n + 7) / 8, 256>>>((const float4*)q, out, n, m, b);
    }

    int mb = m * b;
    passB_kernel<<<(mb + 255) / 256, 256>>>(r, out, m, b);
}

// round 17
// speedup vs baseline: 1.0487x; 1.0248x over previous
#include <cuda_runtime.h>
#include <cuda_fp16.h>

#define HEADS 8
#define D 256
#define NCAP 32768
#define MCAP 327680

// Segment-sum scratch, packed: seg[(node*b + bb)*HEADS + h]. 2MB slack.
__device__ float g_seg[1 << 19];

// fp16 mirror of k (unscaled; q carries the 1/16 softmax scale).
#define K_CAP 10485760
__device__ __half g_kh[K_CAP];

// counting-sort / CSR scratch (16B aligned for int4 access)
__device__ __align__(16) int  g_cnt[NCAP];     // zeroed by scan each call
__device__ __align__(16) int  g_ofs[NCAP + 4]; // CSR row start + sentinel
__device__ __align__(16) int  g_cur[NCAP];     // scatter cursor
// {k_byteoff, ex_byteoff, seg_byteoff, 0} grouped by q-node
__device__ int4 g_edges[MCAP];

// Zero seg; histogram e0; convert k -> fp16.
__global__ void __launch_bounds__(256) prep_kernel(
    const float4* __restrict__ k,
    const int* __restrict__ e0, int m, int n16, int segcount)
{
    int i = blockIdx.x * blockDim.x + threadIdx.x;
    int stride = gridDim.x * blockDim.x;

    for (int s = i; s < segcount; s += stride) g_seg[s] = 0.0f;
    for (int j = i; j < m; j += stride) atomicAdd(&g_cnt[e0[j]], 1);

    uint4* kh = (uint4*)g_kh;
    for (int j = i; j < n16; j += stride) {
        float4 v0 = k[2 * j], v1 = k[2 * j + 1];
        __half2 h0 = __floats2half2_rn(v0.x, v0.y);
        __half2 h1 = __floats2half2_rn(v0.z, v0.w);
        __half2 h2 = __floats2half2_rn(v1.x, v1.y);
        __half2 h3 = __floats2half2_rn(v1.z, v1.w);
        uint4 u;
        u.x = *(unsigned*)&h0; u.y = *(unsigned*)&h1;
        u.z = *(unsigned*)&h2; u.w = *(unsigned*)&h3;
        kh[j] = u;
    }
}

// Single-block exclusive scan, 4 elements/thread (int4). Re-zeroes g_cnt.
__global__ void __launch_bounds__(1024) scan_kernel(int n)
{
    __shared__ int wsum[32];
    __shared__ int wexcl[32];
    __shared__ int s_carry;
    int tid = threadIdx.x, lane = tid & 31, wid = tid >> 5;
    if (tid == 0) s_carry = 0;
    __syncthreads();

    int nt = (n + 4095) >> 12;
    for (int tb = 0; tb < nt; tb++) {
        int i4 = (tb << 12) + (tid << 2);
        int4 c = *(const int4*)&g_cnt[i4];
        *(int4*)&g_cnt[i4] = make_int4(0, 0, 0, 0);
        int lsum = c.x + c.y + c.z + c.w;
        int s = lsum;
        #pragma unroll
        for (int off = 1; off < 32; off <<= 1) {
            int t = __shfl_up_sync(0xffffffffu, s, off);
            if (lane >= off) s += t;
        }
        if (lane == 31) wsum[wid] = s;
        __syncthreads();
        if (wid == 0) {
            int w = wsum[lane];
            int ws = w;
            #pragma unroll
            for (int off = 1; off < 32; off <<= 1) {
                int t = __shfl_up_sync(0xffffffffu, ws, off);
                if (lane >= off) ws += t;
            }
            wexcl[lane] = ws - w;
        }
        __syncthreads();
        int excl = (s - lsum) + wexcl[wid] + s_carry;
        int o0 = excl, o1 = o0 + c.x, o2 = o1 + c.y, o3 = o2 + c.z;
        *(int4*)&g_ofs[i4] = make_int4(o0, o1, o2, o3);
        *(int4*)&g_cur[i4] = make_int4(o0, o1, o2, o3);
        __syncthreads();
        if (tid == 1023) s_carry = excl + lsum;
        __syncthreads();
    }
    if (tid == 0) g_ofs[n] = s_carry;          // sentinel
}

// Scatter edges grouped by q-node, storing precomputed byte offsets.
__global__ void __launch_bounds__(256) scatter_kernel(
    const int* __restrict__ e0, const int* __restrict__ e1,
    const int* __restrict__ r, int m, int b)
{
    int t = blockIdx.x * blockDim.x + threadIdx.x;
    int j0 = t * 4;
    if (j0 >= m) return;

    if (j0 + 4 <= m) {
        int4 q4 = *(const int4*)(e0 + j0);
        int4 k4 = *(const int4*)(e1 + j0);
        int4 r4 = *(const int4*)(r + j0);
        int p0 = atomicAdd(&g_cur[q4.x], 1);
        int p1 = atomicAdd(&g_cur[q4.y], 1);
        int p2 = atomicAdd(&g_cur[q4.z], 1);
        int p3 = atomicAdd(&g_cur[q4.w], 1);
        int b32 = b * 32;
        g_edges[p0] = make_int4(k4.x << 9, (j0 + 0) << 5, r4.x * b32, 0);
        g_edges[p1] = make_int4(k4.y << 9, (j0 + 1) << 5, r4.y * b32, 0);
        g_edges[p2] = make_int4(k4.z << 9, (j0 + 2) << 5, r4.z * b32, 0);
        g_edges[p3] = make_int4(k4.w << 9, (j0 + 3) << 5, r4.w * b32, 0);
    } else {
        for (int j = j0; j < m; j++) {
            int pos = atomicAdd(&g_cur[e0[j]], 1);
            g_edges[pos] = make_int4(e1[j] << 9, j << 5, r[j] * b * 32, 0);
        }
    }
}

// fp16 dot of 16 dims: 8 HFMA2-class ops into one half2 acc, fp32 fix-up.
__device__ __forceinline__ float dot16h(uint4 qa, uint4 qb, uint4 ka, uint4 kb) {
    const __half2* qa2 = (const __half2*)&qa;
    const __half2* qb2 = (const __half2*)&qb;
    const __half2* ka2 = (const __half2*)&ka;
    const __half2* kb2 = (const __half2*)&kb;
    __half2 acc = __hmul2(qa2[0], ka2[0]);
    acc = __hfma2(qa2[1], ka2[1], acc);
    acc = __hfma2(qa2[2], ka2[2], acc);
    acc = __hfma2(qa2[3], ka2[3], acc);
    acc = __hfma2(qb2[0], kb2[0], acc);
    acc = __hfma2(qb2[1], kb2[1], acc);
    acc = __hfma2(qb2[2], kb2[2], acc);
    acc = __hfma2(qb2[3], kb2[3], acc);
    float2 f = __half22float2(acc);
    return f.x + f.y;
}

// A1 (b==2): 2-warp blocks for fine-grained residency turnover (block holds
// the SM until its slowest warp ends; max of 2 degree-draws << max of 8).
// One warp per q-node; lanes = (edge e=lane>>4, head h=(lane>>1)&7,
// half=lane&1); software-pipelined k loads.
__global__ void __launch_bounds__(64) passA1_b2_kernel(
    const float4* __restrict__ q,
    float* __restrict__ ex_out, int n, int m)
{
    __shared__ __align__(16) char qsm[2][2][512];

    int wid = threadIdx.x >> 5, lane = threadIdx.x & 31;
    int v = blockIdx.x * 2 + wid;
    if (v >= n) return;

    int start = g_ofs[v];
    int cnt = g_ofs[v + 1] - start;
    if (cnt == 0) return;

    // --- stage q (both batches) into smem as scaled fp16, chunk-major ---
    {
        long long qrow = (long long)v * (D / 4) + lane * 2;
        long long qbs = (long long)n * (D / 4);
        const float SC = 0.0625f;   // softmax 1/16 folded into q
        int saddr = ((lane & 1) << 8) + ((((lane >> 2) << 1) | ((lane >> 1) & 1)) << 4);
        #pragma unroll
        for (int bb = 0; bb < 2; bb++) {
            float4 a = q[qrow + bb * qbs];
            float4 c = q[qrow + bb * qbs + 1];
            __half2 h0 = __floats2half2_rn(a.x * SC, a.y * SC);
            __half2 h1 = __floats2half2_rn(a.z * SC, a.w * SC);
            __half2 h2 = __floats2half2_rn(c.x * SC, c.y * SC);
            __half2 h3 = __floats2half2_rn(c.z * SC, c.w * SC);
            uint4 u;
            u.x = *(unsigned*)&h0; u.y = *(unsigned*)&h1;
            u.z = *(unsigned*)&h2; u.w = *(unsigned*)&h3;
            *(uint4*)(qsm[wid][bb] + saddr) = u;
        }
    }
    __syncwarp();

    int h = (lane >> 1) & 7;
    int half = lane & 1;
    int e = lane >> 4;

    int rbase = ((h << 1) | half) << 4;
    uint4 q00 = *(const uint4*)(qsm[wid][0] + rbase);
    uint4 q01 = *(const uint4*)(qsm[wid][0] + 256 + rbase);
    uint4 q10 = *(const uint4*)(qsm[wid][1] + rbase);
    uint4 q11 = *(const uint4*)(qsm[wid][1] + 256 + rbase);

    const char* kb = (const char*)g_kh;
    char* exb = (char*)ex_out;
    char* segb = (char*)g_seg;
    int kbs = n << 9;                   // bytes between k batches
    int exb1 = m << 5;                  // batch-1 ex byte offset
    int klo = (h << 6) + (half << 5);   // within-row byte offset of lane's 16 dims
    int h4 = h << 2;
    bool wlane = (half == 0);
    int last = cnt - 1;

    // ---- prologue: load iteration 0 ----
    int idx = e < last ? e : last;
    int4 ed = g_edges[start + idx];
    int ko = ed.x + klo;
    uint4 ka0 = *(const uint4*)(kb + ko);
    uint4 ka1 = *(const uint4*)(kb + ko + 16);
    uint4 kc0 = *(const uint4*)(kb + ko + kbs);
    uint4 kc1 = *(const uint4*)(kb + ko + kbs + 16);

    for (int t = 0; t < cnt; t += 2) {
        // ---- prefetch iteration t+2 (clamped; harmless re-load at tail) ----
        int nidxr = t + 2 + e;
        int nidx = nidxr < last ? nidxr : last;
        int4 edn = g_edges[start + nidx];
        int kon = edn.x + klo;
        uint4 na0 = *(const uint4*)(kb + kon);
        uint4 na1 = *(const uint4*)(kb + kon + 16);
        uint4 nc0 = *(const uint4*)(kb + kon + kbs);
        uint4 nc1 = *(const uint4*)(kb + kon + kbs + 16);

        // ---- compute current pair ----
        float s0 = dot16h(q00, q01, ka0, ka1);
        float s1 = dot16h(q10, q11, kc0, kc1);
        s0 += __shfl_xor_sync(0xffffffffu, s0, 1);
        s1 += __shfl_xor_sync(0xffffffffu, s1, 1);

        // a = dot/sqrt(256) (scale folded into q); global max-shift dropped:
        // ratio is shift-invariant, exp(a) <= ~8, eps below fp32 ulp of denom.
        float ex0 = __expf(s0);
        float ex1 = __expf(s1);

        if (wlane && (t + e < cnt)) {
            *(float*)(exb + ed.y + h4) = ex0;
            *(float*)(exb + ed.y + exb1 + h4) = ex1;
            atomicAdd((float*)(segb + ed.z + h4), ex0);
            atomicAdd((float*)(segb + ed.z + 32 + h4), ex1);
        }

        // ---- rotate pipeline ----
        ed = edn;
        ka0 = na0; ka1 = na1; kc0 = nc0; kc1 = nc1;
    }
}

// Generic-b fallback (correctness path; b==2 uses the kernel above).
__device__ __forceinline__ float dotqk_g(float4 qa, float4 qb, uint4 uk) {
    float s = 0.0f;
    float2 c;
    c = __half22float2(*(const __half2*)&uk.x); s += qa.x * c.x + qa.y * c.y;
    c = __half22float2(*(const __half2*)&uk.y); s += qa.z * c.x + qa.w * c.y;
    c = __half22float2(*(const __half2*)&uk.z); s += qb.x * c.x + qb.y * c.y;
    c = __half22float2(*(const __half2*)&uk.w); s += qb.z * c.x + qb.w * c.y;
    return s;
}

__global__ void __launch_bounds__(256) passA1_gen_kernel(
    const float4* __restrict__ q,
    float* __restrict__ ex_out, int n, int m, int b)
{
    int v = blockIdx.x * (blockDim.x >> 5) + (threadIdx.x >> 5);
    int lane = threadIdx.x & 31;
    if (v >= n) return;

    int start = g_ofs[v];
    int cnt = g_ofs[v + 1] - start;
    if (cnt == 0) return;

    const char* kb = (const char*)g_kh;
    char* exb = (char*)ex_out;
    char* segb = (char*)g_seg;
    int lane16 = lane * 16;
    int kbstride = n << 9;
    bool wr = (lane & 3) == 0;
    int h4 = lane & 28;
    long long qrow = (long long)v * (D / 4) + lane * 2;
    long long qbs = (long long)n * (D / 4);

    for (int t = 0; t < cnt; t++) {
        int4 ed = g_edges[start + t];
        for (int bb = 0; bb < b; bb++) {
            float4 qa = q[qrow + bb * qbs];
            float4 qb = q[qrow + bb * qbs + 1];
            uint4 uk = *(const uint4*)(kb + ed.x + lane16 + bb * kbstride);
            float s = dotqk_g(qa, qb, uk);
            s += __shfl_xor_sync(0xffffffffu, s, 1);
            s += __shfl_xor_sync(0xffffffffu, s, 2);
            float ex = __expf(s * 0.0625f);
            if (wr) {
                *(float*)(exb + ed.y + (long long)bb * (m << 5) + h4) = ex;
                atomicAdd((float*)(segb + ed.z + bb * 32 + h4), ex);
            }
        }
    }
}

// B: one thread per (batch, edge): normalize 8 heads.
__global__ void __launch_bounds__(256) passB_kernel(
    const int* __restrict__ r, float* __restrict__ out, int m, int b)
{
    int i = blockIdx.x * blockDim.x + threadIdx.x;
    if (i >= m * b) return;
    int bb = i / m;
    int mm = i - bb * m;
    int rr = r[mm];

    const float4* segp = (const float4*)&g_seg[(((long long)rr * b + bb) << 3)];
    float4 s0 = segp[0], s1 = segp[1];

    float4* op = (float4*)(out + ((long long)i << 3));
    float4 v0 = op[0], v1 = op[1];

    v0.x /= (s0.x + 1e-16f); v0.y /= (s0.y + 1e-16f);
    v0.z /= (s0.z + 1e-16f); v0.w /= (s0.w + 1e-16f);
    v1.x /= (s1.x + 1e-16f); v1.y /= (s1.y + 1e-16f);
    v1.z /= (s1.z + 1e-16f); v1.w /= (s1.w + 1e-16f);

    op[0] = v0; op[1] = v1;
}

extern "C" void kernel_launch(void* const* d_in, const int* in_sizes, int n_in,
                              void* d_out, int out_size) {
    const float* q = (const float*)d_in[0];
    const float* k = (const float*)d_in[1];
    const int*   e = (const int*)d_in[2];
    const int*   r = (const int*)d_in[3];
    float* out = (float*)d_out;

    int m = in_sizes[3];                    // r has m elements
    int b = out_size / (m * HEADS);         // output is (b, m, HEADS)
    int n = in_sizes[0] / (b * D);          // q is (b, n, D)

    const int* e0 = e;
    const int* e1 = e + m;

    int seg_count = n * b * HEADS;
    int n16 = (b * n * D) / 8;              // 16-byte half chunks of k
    prep_kernel<<<4000, 256>>>((const float4*)k, e0, m, n16, seg_count);

    scan_kernel<<<1, 1024>>>(n);
    scatter_kernel<<<((m + 3) / 4 + 255) / 256, 256>>>(e0, e1, r, m, b);

    if (b == 2) {
        passA1_b2_kernel<<<(n + 1) / 2, 64>>>((const float4*)q, out, n, m);
    } else {
        passA1_gen_kernel<<<(n + 7) / 8, 256>>>((const float4*)q, out, n, m, b);
    }

    int mb = m * b;
    passB_kernel<<<(mb + 255) / 256, 256>>>(r, out, m, b);
}